// round 12
// baseline (speedup 1.0000x reference)
#include <cuda_runtime.h>
#include <math.h>

#define N_NODES 100000
#define N_EDGES 1600000
#define DIM 128
#define OUTC 16
#define WSTRIDE 130                 // padded row stride for transposed W
#define CSR_CAP (N_EDGES + 3 * N_NODES + 32)   // padded CSR capacity

typedef unsigned long long ull;

// ---------------------------------------------------------------------------
// Scratch (__device__ globals: allocation-free rule)
// ---------------------------------------------------------------------------
__device__ float4 g_ht[(size_t)N_NODES * DIM / 4];   // gather output / z scratch
__device__ float4 g_h0[(size_t)N_NODES * DIM / 4];
__device__ float4 g_h1[(size_t)N_NODES * DIM / 4];
__device__ int    g_rowptr[N_NODES + 1];             // padded row starts
__device__ int    g_rowend[N_NODES];                 // true (unpadded) row ends
__device__ int    g_wptr[N_NODES];
__device__ int4   g_csrc4[CSR_CAP / 4];              // src per CSR slot (16B aligned)
__device__ float4 g_cw4[CSR_CAP / 4];                // weight per CSR slot

// ---------------------------------------------------------------------------
// CSR build: zero counts -> histogram -> padded scan -> zero pad -> fill
// ---------------------------------------------------------------------------
__global__ void zero_counts_kernel(int* __restrict__ cnt) {
    int i = blockIdx.x * blockDim.x + threadIdx.x;
    if (i < N_NODES) cnt[i] = 0;
}

__global__ void hist_kernel(const int* __restrict__ dst, int* __restrict__ cnt) {
    int e = blockIdx.x * blockDim.x + threadIdx.x;
    if (e < N_EDGES) atomicAdd(&cnt[dst[e]], 1);
}

// Exclusive scan with per-row padding to multiples of 4.
// rowptr[n] = padded start; rowend[n] = rowptr[n] + true count; wptr = start.
__global__ void scan_kernel(int* __restrict__ cnt_and_wptr,
                            int* __restrict__ rowptr,
                            int* __restrict__ rowend) {
    __shared__ int ssum[1024];
    const int t = threadIdx.x;
    const int per = (N_NODES + 1023) / 1024;          // 98
    const int beg = t * per;
    const int end = (beg + per < N_NODES) ? beg + per : N_NODES;

    int local[104];
    int s = 0;
    for (int i = beg; i < end; i++) {
        int c = cnt_and_wptr[i];
        local[i - beg] = c;
        s += (c + 3) & ~3;                            // padded size
    }
    const int mysum = s;
    ssum[t] = s;
    __syncthreads();

    for (int o = 1; o < 1024; o <<= 1) {
        int v = (t >= o) ? ssum[t - o] : 0;
        __syncthreads();
        ssum[t] += v;
        __syncthreads();
    }
    int off = ssum[t] - mysum;                        // exclusive padded prefix

    for (int i = beg; i < end; i++) {
        rowptr[i] = off;
        rowend[i] = off + local[i - beg];
        cnt_and_wptr[i] = off;
        off += (local[i - beg] + 3) & ~3;
    }
    if (t == 1023) rowptr[N_NODES] = off;             // total padded size
}

__global__ void zero_pad_kernel(int4* __restrict__ csrc4,
                                float4* __restrict__ cw4) {
    const int n = CSR_CAP / 4;
    for (int i = blockIdx.x * blockDim.x + threadIdx.x; i < n;
         i += gridDim.x * blockDim.x) {
        csrc4[i] = make_int4(0, 0, 0, 0);
        cw4[i]   = make_float4(0.f, 0.f, 0.f, 0.f);
    }
}

__global__ void fill_kernel(const int* __restrict__ src,
                            const int* __restrict__ dst,
                            const float* __restrict__ ew,
                            int* __restrict__ wptr,
                            int* __restrict__ csrc,
                            float* __restrict__ cw) {
    int e = blockIdx.x * blockDim.x + threadIdx.x;
    if (e >= N_EDGES) return;
    int pos = atomicAdd(&wptr[dst[e]], 1);
    csrc[pos] = src[e];
    cw[pos]   = ew[e];
}

// ---------------------------------------------------------------------------
// Gather (128-dim): h[n] = (1+eps)*x[n] + sum w_e * x[src_e]
// One warp per node. Rows are padded to multiples of 4 (pad: src=0, w=0),
// so indices/weights load as single int4/float4 and the loop has no tail.
// ---------------------------------------------------------------------------
__global__ void __launch_bounds__(256)
gather_kernel(const float4* __restrict__ x4,
              const int* __restrict__ rowptr,
              const int4* __restrict__ csrc4,
              const float4* __restrict__ cw4,
              const float* __restrict__ eps,
              float4* __restrict__ h4) {
    const int wid  = (blockIdx.x * blockDim.x + threadIdx.x) >> 5;
    if (wid >= N_NODES) return;
    const int lane = threadIdx.x & 31;

    const int beg4 = rowptr[wid] >> 2;                // group index
    const int end4 = rowptr[wid + 1] >> 2;

    float4 a0 = make_float4(0.f, 0.f, 0.f, 0.f);
    float4 a1 = make_float4(0.f, 0.f, 0.f, 0.f);
    float4 a2 = make_float4(0.f, 0.f, 0.f, 0.f);
    float4 a3 = make_float4(0.f, 0.f, 0.f, 0.f);

#pragma unroll 2
    for (int g = beg4; g < end4; g++) {
        const int4   s = csrc4[g];
        const float4 w = cw4[g];
        float4 v0 = x4[(size_t)s.x * (DIM / 4) + lane];
        float4 v1 = x4[(size_t)s.y * (DIM / 4) + lane];
        float4 v2 = x4[(size_t)s.z * (DIM / 4) + lane];
        float4 v3 = x4[(size_t)s.w * (DIM / 4) + lane];
        a0.x += w.x * v0.x; a0.y += w.x * v0.y; a0.z += w.x * v0.z; a0.w += w.x * v0.w;
        a1.x += w.y * v1.x; a1.y += w.y * v1.y; a1.z += w.y * v1.z; a1.w += w.y * v1.w;
        a2.x += w.z * v2.x; a2.y += w.z * v2.y; a2.z += w.z * v2.z; a2.w += w.z * v2.w;
        a3.x += w.w * v3.x; a3.y += w.w * v3.y; a3.z += w.w * v3.z; a3.w += w.w * v3.w;
    }

    const float ep = 1.0f + eps[0];
    float4 xv = x4[(size_t)wid * (DIM / 4) + lane];
    float4 h;
    h.x = ep * xv.x + a0.x + a1.x + a2.x + a3.x;
    h.y = ep * xv.y + a0.y + a1.y + a2.y + a3.y;
    h.z = ep * xv.z + a0.z + a1.z + a2.z + a3.z;
    h.w = ep * xv.w + a0.w + a1.w + a2.w + a3.w;
    h4[(size_t)wid * (DIM / 4) + lane] = h;
}

// ---------------------------------------------------------------------------
// GEMM + bias + relu + L2-normalize using packed fma.rn.f32x2 (FFMA2).
// ---------------------------------------------------------------------------
__global__ void __launch_bounds__(128, 3)
gemm_norm_kernel(const float4* __restrict__ h4,
                 const float* __restrict__ W,
                 const float* __restrict__ b,
                 float4* __restrict__ out4) {
    extern __shared__ float sm[];
    float* sWT = sm;                        // 128 cols x WSTRIDE
    float* sH  = sm + DIM * WSTRIDE;        // 16 x 128 (i-major)
    float* sR  = sH + 16 * DIM;             // 64

    const int t    = threadIdx.x;
    const int lane = t & 31;
    const int warp = t >> 5;

    for (int i = t; i < DIM * DIM; i += 128) {
        const int k = i >> 7;
        const int c = i & 127;
        sWT[c * WSTRIDE + k] = W[i];
    }

    const float bias = b[t];
    const float* wrow = sWT + t * WSTRIDE;

    const int ntiles = N_NODES / 16;        // 6250
    for (int tile = blockIdx.x; tile < ntiles; tile += gridDim.x) {
        const int n0 = tile * 16;
        __syncthreads();

        for (int i = t; i < 16 * DIM / 4; i += 128)
            reinterpret_cast<float4*>(sH)[i] = h4[(size_t)n0 * (DIM / 4) + i];
        __syncthreads();

        ull acc2[16];
#pragma unroll
        for (int i = 0; i < 16; i++) acc2[i] = 0ULL;

#pragma unroll 4
        for (int k = 0; k < DIM; k += 2) {
            const ull wp = *reinterpret_cast<const ull*>(wrow + k);
#pragma unroll
            for (int i = 0; i < 16; i++) {
                const ull hp = *reinterpret_cast<const ull*>(sH + i * DIM + k);
                asm("fma.rn.f32x2 %0, %1, %2, %0;"
                    : "+l"(acc2[i]) : "l"(hp), "l"(wp));
            }
        }

        float y[16];
#pragma unroll
        for (int i = 0; i < 16; i++) {
            const float lo = __uint_as_float((unsigned)(acc2[i] & 0xffffffffu));
            const float hi = __uint_as_float((unsigned)(acc2[i] >> 32));
            y[i] = fmaxf(lo + hi + bias, 0.f);
        }

#pragma unroll
        for (int i = 0; i < 16; i++) {
            float s = y[i] * y[i];
#pragma unroll
            for (int o = 16; o > 0; o >>= 1)
                s += __shfl_xor_sync(0xffffffffu, s, o);
            if (lane == 0) sR[warp * 16 + i] = s;
        }
        __syncthreads();

#pragma unroll
        for (int i = 0; i < 16; i++) {
            float ns  = sR[i] + sR[16 + i] + sR[32 + i] + sR[48 + i];
            float inv = 1.0f / fmaxf(sqrtf(ns), 1e-12f);
            reinterpret_cast<float*>(out4)[(size_t)(n0 + i) * DIM + t] = y[i] * inv;
        }
    }
}

// ---------------------------------------------------------------------------
// z = h1 @ W2  (100k x 128 @ 128 x 16). One warp per node.
// ---------------------------------------------------------------------------
__global__ void __launch_bounds__(256)
zmat_kernel(const float4* __restrict__ h4,
            const float* __restrict__ W,
            float* __restrict__ z) {
    __shared__ alignas(16) float sWt[OUTC * DIM];   // sWt[j*128+k] = W[k][j]
    const int t = threadIdx.x;
    for (int i = t; i < OUTC * DIM; i += blockDim.x) {
        int j = i / DIM, k = i % DIM;
        sWt[i] = W[k * OUTC + j];
    }
    __syncthreads();

    const int wid  = (blockIdx.x * blockDim.x + t) >> 5;
    if (wid >= N_NODES) return;
    const int lane = t & 31;

    float4 h = h4[(size_t)wid * (DIM / 4) + lane];

    float v[OUTC];
#pragma unroll
    for (int j = 0; j < OUTC; j++) {
        float4 w4 = reinterpret_cast<float4*>(sWt + j * DIM)[lane];
        v[j] = h.x * w4.x + h.y * w4.y + h.z * w4.z + h.w * w4.w;
#pragma unroll
        for (int o = 16; o > 0; o >>= 1)
            v[j] += __shfl_xor_sync(0xffffffffu, v[j], o);
    }
    if (lane == 0) {
        float4* zp = reinterpret_cast<float4*>(z + (size_t)wid * OUTC);
#pragma unroll
        for (int q = 0; q < 4; q++)
            zp[q] = make_float4(v[q * 4], v[q * 4 + 1], v[q * 4 + 2], v[q * 4 + 3]);
    }
}

// ---------------------------------------------------------------------------
// Final gather in 16-dim z-space (UNWEIGHTED -> must use true row ends,
// not padded) + bias + relu + softmax. One warp per node.
// ---------------------------------------------------------------------------
__global__ void __launch_bounds__(256)
final_gather_kernel(const float* __restrict__ z,
                    const int* __restrict__ rowptr,
                    const int* __restrict__ rowend,
                    const int* __restrict__ csrc,
                    const float* __restrict__ b,
                    const float* __restrict__ eps,
                    float* __restrict__ logits,
                    float* __restrict__ probs) {
    const int wid  = (blockIdx.x * blockDim.x + threadIdx.x) >> 5;
    if (wid >= N_NODES) return;
    const int lane = threadIdx.x & 31;
    const int l16  = lane & 15;

    const int beg = rowptr[wid];
    const int end = rowend[wid];

    float a0 = 0.f, a1 = 0.f, a2 = 0.f, a3 = 0.f;
    int i = beg;
    for (; i + 3 < end; i += 4) {
        const int s0 = csrc[i],     s1 = csrc[i + 1];
        const int s2 = csrc[i + 2], s3 = csrc[i + 3];
        a0 += z[(size_t)s0 * OUTC + l16];
        a1 += z[(size_t)s1 * OUTC + l16];
        a2 += z[(size_t)s2 * OUTC + l16];
        a3 += z[(size_t)s3 * OUTC + l16];
    }
    for (; i < end; i++)
        a0 += z[(size_t)csrc[i] * OUTC + l16];

    const float ep = 1.0f + eps[0];
    float v = ep * z[(size_t)wid * OUTC + l16] + a0 + a1 + a2 + a3 + b[l16];
    v = fmaxf(v, 0.f);

    float mx = v;
#pragma unroll
    for (int o = 8; o > 0; o >>= 1)
        mx = fmaxf(mx, __shfl_xor_sync(0xffffffffu, mx, o));
    float ex = expf(v - mx);
    float se = ex;
#pragma unroll
    for (int o = 8; o > 0; o >>= 1)
        se += __shfl_xor_sync(0xffffffffu, se, o);

    if (lane < 16) {
        logits[(size_t)wid * OUTC + l16] = v;
        probs [(size_t)wid * OUTC + l16] = ex / se;
    }
}

// ---------------------------------------------------------------------------
// Launch — inputs bound by SIZE (permutation-proof).
// ---------------------------------------------------------------------------
extern "C" void kernel_launch(void* const* d_in, const int* in_sizes, int n_in,
                              void* d_out, int out_size) {
    const float* x  = nullptr;
    const int*   ei = nullptr;
    const float* ew = nullptr;
    const float* Wp[3] = {nullptr, nullptr, nullptr};
    const float* Bp[3] = {nullptr, nullptr, nullptr};
    const float* Ep[3] = {nullptr, nullptr, nullptr};
    int wi = 0, bi = 0, epi = 0;

    for (int i = 0; i < n_in; i++) {
        switch (in_sizes[i]) {
            case N_NODES * DIM: x  = (const float*)d_in[i]; break;
            case 2 * N_EDGES:   ei = (const int*)d_in[i];   break;
            case N_EDGES:       ew = (const float*)d_in[i]; break;
            case DIM * DIM:     if (wi < 2) Wp[wi++] = (const float*)d_in[i]; break;
            case DIM * OUTC:    Wp[2] = (const float*)d_in[i]; break;
            case DIM:           if (bi < 2) Bp[bi++] = (const float*)d_in[i]; break;
            case OUTC:          Bp[2] = (const float*)d_in[i]; break;
            case 1:             if (epi < 3) Ep[epi++] = (const float*)d_in[i]; break;
            default: break;
        }
    }

    float* out_logits = (float*)d_out;
    float* out_probs  = out_logits + (size_t)N_NODES * OUTC;

    float4 *ht, *h0, *h1;
    int *rowptr, *rowend, *wptr;
    int4 *csrc4;
    float4 *cw4;
    cudaGetSymbolAddress((void**)&ht,     g_ht);
    cudaGetSymbolAddress((void**)&h0,     g_h0);
    cudaGetSymbolAddress((void**)&h1,     g_h1);
    cudaGetSymbolAddress((void**)&rowptr, g_rowptr);
    cudaGetSymbolAddress((void**)&rowend, g_rowend);
    cudaGetSymbolAddress((void**)&wptr,   g_wptr);
    cudaGetSymbolAddress((void**)&csrc4,  g_csrc4);
    cudaGetSymbolAddress((void**)&cw4,    g_cw4);

    const int* src = ei;             // row 0
    const int* dst = ei + N_EDGES;   // row 1

    const int smem = (DIM * WSTRIDE + 16 * DIM + 64) * sizeof(float);  // ~75 KB
    cudaFuncSetAttribute(gemm_norm_kernel,
                         cudaFuncAttributeMaxDynamicSharedMemorySize, smem);

    const float4* x4 = (const float4*)x;
    const int ngrid = (N_NODES * 32 + 255) / 256;   // warp-per-node grids

    // ---- CSR build (padded rows), reused for all 3 layers ----
    zero_counts_kernel<<<(N_NODES + 255) / 256, 256>>>(wptr);
    hist_kernel<<<(N_EDGES + 255) / 256, 256>>>(dst, wptr);
    scan_kernel<<<1, 1024>>>(wptr, rowptr, rowend);
    zero_pad_kernel<<<640, 256>>>(csrc4, cw4);
    fill_kernel<<<(N_EDGES + 255) / 256, 256>>>(src, dst, ew, wptr,
                                                (int*)csrc4, (float*)cw4);

    // ---- Layer 0 ----
    gather_kernel<<<ngrid, 256>>>(x4, rowptr, csrc4, cw4, Ep[0], ht);
    gemm_norm_kernel<<<444, 128, smem>>>(ht, Wp[0], Bp[0], h0);

    // ---- Layer 1 ----
    gather_kernel<<<ngrid, 256>>>(h0, rowptr, csrc4, cw4, Ep[1], ht);
    gemm_norm_kernel<<<444, 128, smem>>>(ht, Wp[1], Bp[1], h1);

    // ---- Layer 2: z = h1@W2, gather in 16-dim, softmax ----
    float* zbuf = (float*)ht;   // reuse scratch
    zmat_kernel<<<ngrid, 256>>>(h1, Wp[2], zbuf);
    final_gather_kernel<<<ngrid, 256>>>(zbuf, rowptr, rowend, (int*)csrc4,
                                        Bp[2], Ep[2], out_logits, out_probs);
}

// round 14
// speedup vs baseline: 1.0966x; 1.0966x over previous
#include <cuda_runtime.h>
#include <math.h>

#define N_NODES 100000
#define N_EDGES 1600000
#define DIM 128
#define OUTC 16
#define WSTRIDE 130   // padded row stride for transposed W (LDS.64-aligned)
#define STAGE_CAP 2048

typedef unsigned long long ull;

// ---------------------------------------------------------------------------
// Scratch (__device__ globals: allocation-free rule)
// ---------------------------------------------------------------------------
__device__ float4 g_ht[(size_t)N_NODES * DIM / 4];   // gather output / z scratch
__device__ float4 g_h0[(size_t)N_NODES * DIM / 4];
__device__ float4 g_h1[(size_t)N_NODES * DIM / 4];
__device__ int    g_rowptr[N_NODES + 1];
__device__ int    g_wptr[N_NODES];
__device__ int    g_csrc[N_EDGES];
__device__ float  g_cw[N_EDGES];

// ---------------------------------------------------------------------------
// CSR build: zero counts -> histogram -> scan -> fill   (unpadded, as R9)
// ---------------------------------------------------------------------------
__global__ void zero_counts_kernel(int* __restrict__ cnt) {
    int i = blockIdx.x * blockDim.x + threadIdx.x;
    if (i < N_NODES) cnt[i] = 0;
}

__global__ void hist_kernel(const int* __restrict__ dst, int* __restrict__ cnt) {
    int e = blockIdx.x * blockDim.x + threadIdx.x;
    if (e < N_EDGES) atomicAdd(&cnt[dst[e]], 1);
}

__global__ void scan_kernel(int* __restrict__ cnt_and_wptr,
                            int* __restrict__ rowptr) {
    __shared__ int ssum[1024];
    const int t = threadIdx.x;
    const int per = (N_NODES + 1023) / 1024;          // 98
    const int beg = t * per;
    const int end = (beg + per < N_NODES) ? beg + per : N_NODES;

    int local[104];
    int s = 0;
    for (int i = beg; i < end; i++) { local[i - beg] = cnt_and_wptr[i]; s += local[i - beg]; }
    const int mysum = s;
    ssum[t] = s;
    __syncthreads();

    for (int o = 1; o < 1024; o <<= 1) {
        int v = (t >= o) ? ssum[t - o] : 0;
        __syncthreads();
        ssum[t] += v;
        __syncthreads();
    }
    int off = ssum[t] - mysum;

    for (int i = beg; i < end; i++) {
        rowptr[i] = off;
        cnt_and_wptr[i] = off;
        off += local[i - beg];
    }
    if (t == 1023) rowptr[N_NODES] = N_EDGES;
}

__global__ void fill_kernel(const int* __restrict__ src,
                            const int* __restrict__ dst,
                            const float* __restrict__ ew,
                            int* __restrict__ wptr,
                            int* __restrict__ csrc,
                            float* __restrict__ cw) {
    int e = blockIdx.x * blockDim.x + threadIdx.x;
    if (e >= N_EDGES) return;
    int pos = atomicAdd(&wptr[dst[e]], 1);
    csrc[pos] = src[e];
    cw[pos]   = ew[e];
}

// ---------------------------------------------------------------------------
// Gather (128-dim): h[n] = (1+eps)*x[n] + sum w_e * x[src_e]
// Block of 8 warps = 8 nodes. Step 1: cooperatively stage all (idx, w)
// pairs for the block's nodes into SMEM (coalesced, chain-free).
// Step 2: each warp walks its node's edges with indices from LDS, so the
// only global dependent load is the row itself.
// ---------------------------------------------------------------------------
__global__ void __launch_bounds__(256)
gather_kernel(const float4* __restrict__ x4,
              const int* __restrict__ rowptr,
              const int* __restrict__ csrc,
              const float* __restrict__ cw,
              const float* __restrict__ eps,
              float4* __restrict__ h4) {
    __shared__ int   sIdx[STAGE_CAP];
    __shared__ float sW[STAGE_CAP];

    const int tid   = threadIdx.x;
    const int warp  = tid >> 5;
    const int lane  = tid & 31;
    const int node0 = blockIdx.x * 8;
    const int n     = node0 + warp;

    const int gbeg = rowptr[node0];
    const int gend = rowptr[node0 + 8];
    const int tot  = gend - gbeg;

    const int beg = rowptr[n];
    const int end = rowptr[n + 1];

    float4 a0 = make_float4(0.f, 0.f, 0.f, 0.f);
    float4 a1 = make_float4(0.f, 0.f, 0.f, 0.f);
    float4 a2 = make_float4(0.f, 0.f, 0.f, 0.f);
    float4 a3 = make_float4(0.f, 0.f, 0.f, 0.f);

    if (tot <= STAGE_CAP) {
        // ---- Stage indices/weights into SMEM (coalesced) ----
        for (int i = tid; i < tot; i += 256) {
            sIdx[i] = csrc[gbeg + i];
            sW[i]   = cw[gbeg + i];
        }
        __syncthreads();

        const int rbeg = beg - gbeg;
        const int rend = end - gbeg;
        int i = rbeg;
        for (; i + 3 < rend; i += 4) {
            const int s0 = sIdx[i],     s1 = sIdx[i + 1];
            const int s2 = sIdx[i + 2], s3 = sIdx[i + 3];
            const float w0 = sW[i],     w1 = sW[i + 1];
            const float w2 = sW[i + 2], w3 = sW[i + 3];
            float4 v0 = x4[(size_t)s0 * (DIM / 4) + lane];
            float4 v1 = x4[(size_t)s1 * (DIM / 4) + lane];
            float4 v2 = x4[(size_t)s2 * (DIM / 4) + lane];
            float4 v3 = x4[(size_t)s3 * (DIM / 4) + lane];
            a0.x += w0 * v0.x; a0.y += w0 * v0.y; a0.z += w0 * v0.z; a0.w += w0 * v0.w;
            a1.x += w1 * v1.x; a1.y += w1 * v1.y; a1.z += w1 * v1.z; a1.w += w1 * v1.w;
            a2.x += w2 * v2.x; a2.y += w2 * v2.y; a2.z += w2 * v2.z; a2.w += w2 * v2.w;
            a3.x += w3 * v3.x; a3.y += w3 * v3.y; a3.z += w3 * v3.z; a3.w += w3 * v3.w;
        }
        for (; i < rend; i++) {
            const int s0 = sIdx[i];
            const float w0 = sW[i];
            float4 v0 = x4[(size_t)s0 * (DIM / 4) + lane];
            a0.x += w0 * v0.x; a0.y += w0 * v0.y; a0.z += w0 * v0.z; a0.w += w0 * v0.w;
        }
    } else {
        // ---- Fallback (statistically unreachable): direct gmem loop ----
        int i = beg;
        for (; i + 3 < end; i += 4) {
            const int s0 = csrc[i],     s1 = csrc[i + 1];
            const int s2 = csrc[i + 2], s3 = csrc[i + 3];
            const float w0 = cw[i],     w1 = cw[i + 1];
            const float w2 = cw[i + 2], w3 = cw[i + 3];
            float4 v0 = x4[(size_t)s0 * (DIM / 4) + lane];
            float4 v1 = x4[(size_t)s1 * (DIM / 4) + lane];
            float4 v2 = x4[(size_t)s2 * (DIM / 4) + lane];
            float4 v3 = x4[(size_t)s3 * (DIM / 4) + lane];
            a0.x += w0 * v0.x; a0.y += w0 * v0.y; a0.z += w0 * v0.z; a0.w += w0 * v0.w;
            a1.x += w1 * v1.x; a1.y += w1 * v1.y; a1.z += w1 * v1.z; a1.w += w1 * v1.w;
            a2.x += w2 * v2.x; a2.y += w2 * v2.y; a2.z += w2 * v2.z; a2.w += w2 * v2.w;
            a3.x += w3 * v3.x; a3.y += w3 * v3.y; a3.z += w3 * v3.z; a3.w += w3 * v3.w;
        }
        for (; i < end; i++) {
            const int s0 = csrc[i];
            const float w0 = cw[i];
            float4 v0 = x4[(size_t)s0 * (DIM / 4) + lane];
            a0.x += w0 * v0.x; a0.y += w0 * v0.y; a0.z += w0 * v0.z; a0.w += w0 * v0.w;
        }
    }

    const float ep = 1.0f + eps[0];
    float4 xv = x4[(size_t)n * (DIM / 4) + lane];
    float4 h;
    h.x = ep * xv.x + a0.x + a1.x + a2.x + a3.x;
    h.y = ep * xv.y + a0.y + a1.y + a2.y + a3.y;
    h.z = ep * xv.z + a0.z + a1.z + a2.z + a3.z;
    h.w = ep * xv.w + a0.w + a1.w + a2.w + a3.w;
    h4[(size_t)n * (DIM / 4) + lane] = h;
}

// ---------------------------------------------------------------------------
// GEMM + bias + relu + L2-normalize using packed fma.rn.f32x2 (FFMA2).
// ---------------------------------------------------------------------------
__global__ void __launch_bounds__(128, 3)
gemm_norm_kernel(const float4* __restrict__ h4,
                 const float* __restrict__ W,
                 const float* __restrict__ b,
                 float4* __restrict__ out4) {
    extern __shared__ float sm[];
    float* sWT = sm;                        // 128 cols x WSTRIDE
    float* sH  = sm + DIM * WSTRIDE;        // 16 x 128 (i-major)
    float* sR  = sH + 16 * DIM;             // 64

    const int t    = threadIdx.x;
    const int lane = t & 31;
    const int warp = t >> 5;

    for (int i = t; i < DIM * DIM; i += 128) {
        const int k = i >> 7;
        const int c = i & 127;
        sWT[c * WSTRIDE + k] = W[i];
    }

    const float bias = b[t];
    const float* wrow = sWT + t * WSTRIDE;

    const int ntiles = N_NODES / 16;        // 6250
    for (int tile = blockIdx.x; tile < ntiles; tile += gridDim.x) {
        const int n0 = tile * 16;
        __syncthreads();

        for (int i = t; i < 16 * DIM / 4; i += 128)
            reinterpret_cast<float4*>(sH)[i] = h4[(size_t)n0 * (DIM / 4) + i];
        __syncthreads();

        ull acc2[16];
#pragma unroll
        for (int i = 0; i < 16; i++) acc2[i] = 0ULL;

#pragma unroll 4
        for (int k = 0; k < DIM; k += 2) {
            const ull wp = *reinterpret_cast<const ull*>(wrow + k);
#pragma unroll
            for (int i = 0; i < 16; i++) {
                const ull hp = *reinterpret_cast<const ull*>(sH + i * DIM + k);
                asm("fma.rn.f32x2 %0, %1, %2, %0;"
                    : "+l"(acc2[i]) : "l"(hp), "l"(wp));
            }
        }

        float y[16];
#pragma unroll
        for (int i = 0; i < 16; i++) {
            const float lo = __uint_as_float((unsigned)(acc2[i] & 0xffffffffu));
            const float hi = __uint_as_float((unsigned)(acc2[i] >> 32));
            y[i] = fmaxf(lo + hi + bias, 0.f);
        }

#pragma unroll
        for (int i = 0; i < 16; i++) {
            float s = y[i] * y[i];
#pragma unroll
            for (int o = 16; o > 0; o >>= 1)
                s += __shfl_xor_sync(0xffffffffu, s, o);
            if (lane == 0) sR[warp * 16 + i] = s;
        }
        __syncthreads();

#pragma unroll
        for (int i = 0; i < 16; i++) {
            float ns  = sR[i] + sR[16 + i] + sR[32 + i] + sR[48 + i];
            float inv = 1.0f / fmaxf(sqrtf(ns), 1e-12f);
            reinterpret_cast<float*>(out4)[(size_t)(n0 + i) * DIM + t] = y[i] * inv;
        }
    }
}

// ---------------------------------------------------------------------------
// z = h1 @ W2  (100k x 128 @ 128 x 16). One warp per node.
// ---------------------------------------------------------------------------
__global__ void __launch_bounds__(256)
zmat_kernel(const float4* __restrict__ h4,
            const float* __restrict__ W,
            float* __restrict__ z) {
    __shared__ alignas(16) float sWt[OUTC * DIM];   // sWt[j*128+k] = W[k][j]
    const int t = threadIdx.x;
    for (int i = t; i < OUTC * DIM; i += blockDim.x) {
        int j = i / DIM, k = i % DIM;
        sWt[i] = W[k * OUTC + j];
    }
    __syncthreads();

    const int wid  = (blockIdx.x * blockDim.x + t) >> 5;
    if (wid >= N_NODES) return;
    const int lane = t & 31;

    float4 h = h4[(size_t)wid * (DIM / 4) + lane];

    float v[OUTC];
#pragma unroll
    for (int j = 0; j < OUTC; j++) {
        float4 w4 = reinterpret_cast<float4*>(sWt + j * DIM)[lane];
        v[j] = h.x * w4.x + h.y * w4.y + h.z * w4.z + h.w * w4.w;
#pragma unroll
        for (int o = 16; o > 0; o >>= 1)
            v[j] += __shfl_xor_sync(0xffffffffu, v[j], o);
    }
    if (lane == 0) {
        float4* zp = reinterpret_cast<float4*>(z + (size_t)wid * OUTC);
#pragma unroll
        for (int q = 0; q < 4; q++)
            zp[q] = make_float4(v[q * 4], v[q * 4 + 1], v[q * 4 + 2], v[q * 4 + 3]);
    }
}

// ---------------------------------------------------------------------------
// Final gather in 16-dim z-space + bias + relu + softmax. One warp per node.
// ---------------------------------------------------------------------------
__global__ void __launch_bounds__(256)
final_gather_kernel(const float* __restrict__ z,
                    const int* __restrict__ rowptr,
                    const int* __restrict__ csrc,
                    const float* __restrict__ b,
                    const float* __restrict__ eps,
                    float* __restrict__ logits,
                    float* __restrict__ probs) {
    const int wid  = (blockIdx.x * blockDim.x + threadIdx.x) >> 5;
    if (wid >= N_NODES) return;
    const int lane = threadIdx.x & 31;
    const int l16  = lane & 15;

    const int beg = rowptr[wid];
    const int end = rowptr[wid + 1];

    float a0 = 0.f, a1 = 0.f, a2 = 0.f, a3 = 0.f;
    int i = beg;
    for (; i + 3 < end; i += 4) {
        const int s0 = csrc[i],     s1 = csrc[i + 1];
        const int s2 = csrc[i + 2], s3 = csrc[i + 3];
        a0 += z[(size_t)s0 * OUTC + l16];
        a1 += z[(size_t)s1 * OUTC + l16];
        a2 += z[(size_t)s2 * OUTC + l16];
        a3 += z[(size_t)s3 * OUTC + l16];
    }
    for (; i < end; i++)
        a0 += z[(size_t)csrc[i] * OUTC + l16];

    const float ep = 1.0f + eps[0];
    float v = ep * z[(size_t)wid * OUTC + l16] + a0 + a1 + a2 + a3 + b[l16];
    v = fmaxf(v, 0.f);

    float mx = v;
#pragma unroll
    for (int o = 8; o > 0; o >>= 1)
        mx = fmaxf(mx, __shfl_xor_sync(0xffffffffu, mx, o));
    float ex = expf(v - mx);
    float se = ex;
#pragma unroll
    for (int o = 8; o > 0; o >>= 1)
        se += __shfl_xor_sync(0xffffffffu, se, o);

    if (lane < 16) {
        logits[(size_t)wid * OUTC + l16] = v;
        probs [(size_t)wid * OUTC + l16] = ex / se;
    }
}

// ---------------------------------------------------------------------------
// Launch — inputs bound by SIZE (permutation-proof).
// ---------------------------------------------------------------------------
extern "C" void kernel_launch(void* const* d_in, const int* in_sizes, int n_in,
                              void* d_out, int out_size) {
    const float* x  = nullptr;
    const int*   ei = nullptr;
    const float* ew = nullptr;
    const float* Wp[3] = {nullptr, nullptr, nullptr};
    const float* Bp[3] = {nullptr, nullptr, nullptr};
    const float* Ep[3] = {nullptr, nullptr, nullptr};
    int wi = 0, bi = 0, epi = 0;

    for (int i = 0; i < n_in; i++) {
        switch (in_sizes[i]) {
            case N_NODES * DIM: x  = (const float*)d_in[i]; break;
            case 2 * N_EDGES:   ei = (const int*)d_in[i];   break;
            case N_EDGES:       ew = (const float*)d_in[i]; break;
            case DIM * DIM:     if (wi < 2) Wp[wi++] = (const float*)d_in[i]; break;
            case DIM * OUTC:    Wp[2] = (const float*)d_in[i]; break;
            case DIM:           if (bi < 2) Bp[bi++] = (const float*)d_in[i]; break;
            case OUTC:          Bp[2] = (const float*)d_in[i]; break;
            case 1:             if (epi < 3) Ep[epi++] = (const float*)d_in[i]; break;
            default: break;
        }
    }

    float* out_logits = (float*)d_out;
    float* out_probs  = out_logits + (size_t)N_NODES * OUTC;

    float4 *ht, *h0, *h1;
    int *rowptr, *wptr, *csrc;
    float *cw;
    cudaGetSymbolAddress((void**)&ht,     g_ht);
    cudaGetSymbolAddress((void**)&h0,     g_h0);
    cudaGetSymbolAddress((void**)&h1,     g_h1);
    cudaGetSymbolAddress((void**)&rowptr, g_rowptr);
    cudaGetSymbolAddress((void**)&wptr,   g_wptr);
    cudaGetSymbolAddress((void**)&csrc,   g_csrc);
    cudaGetSymbolAddress((void**)&cw,     g_cw);

    const int* src = ei;             // row 0
    const int* dst = ei + N_EDGES;   // row 1

    const int smem = (DIM * WSTRIDE + 16 * DIM + 64) * sizeof(float);  // ~75 KB
    cudaFuncSetAttribute(gemm_norm_kernel,
                         cudaFuncAttributeMaxDynamicSharedMemorySize, smem);

    const float4* x4 = (const float4*)x;
    const int ngrid  = (N_NODES * 32 + 255) / 256;   // warp-per-node grids
    const int ggrid  = N_NODES / 8;                  // 12500 (8 nodes/block)

    // ---- CSR build (by destination), reused for all 3 layers ----
    zero_counts_kernel<<<(N_NODES + 255) / 256, 256>>>(wptr);
    hist_kernel<<<(N_EDGES + 255) / 256, 256>>>(dst, wptr);
    scan_kernel<<<1, 1024>>>(wptr, rowptr);
    fill_kernel<<<(N_EDGES + 255) / 256, 256>>>(src, dst, ew, wptr, csrc, cw);

    // ---- Layer 0 ----
    gather_kernel<<<ggrid, 256>>>(x4, rowptr, csrc, cw, Ep[0], ht);
    gemm_norm_kernel<<<444, 128, smem>>>(ht, Wp[0], Bp[0], h0);

    // ---- Layer 1 ----
    gather_kernel<<<ggrid, 256>>>(h0, rowptr, csrc, cw, Ep[1], ht);
    gemm_norm_kernel<<<444, 128, smem>>>(ht, Wp[1], Bp[1], h1);

    // ---- Layer 2: z = h1@W2, gather in 16-dim, softmax ----
    float* zbuf = (float*)ht;   // reuse scratch
    zmat_kernel<<<ngrid, 256>>>(h1, Wp[2], zbuf);
    final_gather_kernel<<<ngrid, 256>>>(zbuf, rowptr, csrc, Bp[2], Ep[2],
                                        out_logits, out_probs);
}